// round 7
// baseline (speedup 1.0000x reference)
#include <cuda_runtime.h>
#include <cstdint>

#define BATCH   2
#define HEADS   16
#define NTOK    2048
#define DK      64
#define BH      (BATCH*HEADS)
#define QT      16              // queries per CTA
#define KT      128             // key/value tile rows
#define DS      68              // padded smem row stride (floats)
#define NTILES  (NTOK/KT)       // 16
#define THREADS 256
#define SCALE   0.125f          // 1/sqrt(64)

// smem layout (in floats)
#define SM_S    0                       // QT*NTOK      = 32768
#define SM_QT   (QT*NTOK)               // DK*16        = 1024 (Q transposed, pre-scaled)
#define SM_KV   (SM_QT + DK*16)         // 2*KT*DS      = 17408 (double-buffered K/V tile)
#define SM_RL   (SM_KV + 2*KT*DS)       // QT           = 16 (1/rowsum)
#define SM_TOTAL (SM_RL + QT)           // 51216 floats = 204864 bytes

typedef unsigned long long ull;

__device__ __forceinline__ ull dup2(float x) {
    ull r; asm("mov.b64 %0, {%1,%1};" : "=l"(r) : "f"(x)); return r;
}
__device__ __forceinline__ void fma2(ull &d, ull a, ull b) {
    asm("fma.rn.f32x2 %0, %1, %2, %0;" : "+l"(d) : "l"(a), "l"(b));
}
__device__ __forceinline__ void unpack2(ull v, float &x, float &y) {
    asm("mov.b64 {%0,%1}, %2;" : "=f"(x), "=f"(y) : "l"(v));
}
__device__ __forceinline__ ull pack2(float x, float y) {
    ull r; asm("mov.b64 %0, {%1,%2};" : "=l"(r) : "f"(x), "f"(y)); return r;
}
__device__ __forceinline__ void lds_v2u64(ull &a, ull &b, uint32_t addr) {
    asm volatile("ld.shared.v2.u64 {%0,%1}, [%2];" : "=l"(a), "=l"(b) : "r"(addr));
}
__device__ __forceinline__ void sts_u64(uint32_t addr, ull v) {
    asm volatile("st.shared.b64 [%0], %1;" :: "r"(addr), "l"(v) : "memory");
}
__device__ __forceinline__ void cpasync16(uint32_t dst, const float* src) {
    asm volatile("cp.async.cg.shared.global [%0], [%1], 16;" :: "r"(dst), "l"(src) : "memory");
}
// streaming (evict-first) 128-bit store: keeps attn traffic from thrashing L2
__device__ __forceinline__ void stg_cs128(float* p, float4 v) {
    asm volatile("st.global.cs.v4.f32 [%0], {%1,%2,%3,%4};"
                 :: "l"(p), "f"(v.x), "f"(v.y), "f"(v.z), "f"(v.w) : "memory");
}

// Load one KT x DK tile (row-major, stride DS floats) into smem buffer `buf` via cp.async.
__device__ __forceinline__ void load_tile_async(uint32_t kv_base, int buf, const float* __restrict__ src) {
    uint32_t dst0 = kv_base + (uint32_t)(buf * KT * DS * 4);
    int tid = threadIdx.x;
#pragma unroll
    for (int i = 0; i < (KT * DK / 4) / THREADS; i++) {
        int idx = tid + i * THREADS;
        int r = idx >> 4;
        int c = (idx & 15) << 2;
        cpasync16(dst0 + (uint32_t)((r * DS + c) * 4), src + r * DK + c);
    }
    asm volatile("cp.async.commit_group;" ::: "memory");
}

extern __shared__ float sm[];

__global__ void __launch_bounds__(THREADS, 1)
sdpa_kernel(const float* __restrict__ Q, const float* __restrict__ K,
            const float* __restrict__ V, float* __restrict__ Out,
            float* __restrict__ Attn, int write_attn)
{
    const int tid = threadIdx.x;
    const int bh  = blockIdx.y;
    const int q0  = blockIdx.x * QT;

    const float* Qg = Q + ((size_t)bh * NTOK + q0) * DK;
    const float* Kg = K + (size_t)bh * NTOK * DK;
    const float* Vg = V + (size_t)bh * NTOK * DK;

    float* S  = sm + SM_S;
    float* Qt = sm + SM_QT;
    float* KV = sm + SM_KV;
    float* RL = sm + SM_RL;
    uint32_t kv_base = (uint32_t)__cvta_generic_to_shared(KV);
    uint32_t qt_base = (uint32_t)__cvta_generic_to_shared(Qt);
    uint32_t s_base  = (uint32_t)__cvta_generic_to_shared(S);

    // Prefetch K tile 0
    load_tile_async(kv_base, 0, Kg);

    // Q transpose + pre-scale: Qt[d][q] = Q[q][d] * SCALE. 256 threads, one float4 each.
    {
        int q  = tid & 15;
        int d0 = (tid >> 4) << 2;
        float4 v = *(const float4*)(Qg + q * DK + d0);
        Qt[(d0 + 0) * 16 + q] = v.x * SCALE;
        Qt[(d0 + 1) * 16 + q] = v.y * SCALE;
        Qt[(d0 + 2) * 16 + q] = v.z * SCALE;
        Qt[(d0 + 3) * 16 + q] = v.w * SCALE;
    }

    // ---- QK^T: each thread computes 4 queries x 2 keys (packed f32x2) ----
    const int qg = tid & 3;   // query pair group: queries 4*qg .. 4*qg+3
    const int kg = tid >> 2;  // keys 2*kg, 2*kg+1

    for (int t = 0; t < NTILES; t++) {
        if (t + 1 < NTILES) {
            load_tile_async(kv_base, (t + 1) & 1, Kg + (size_t)(t + 1) * KT * DK);
            asm volatile("cp.async.wait_group 1;" ::: "memory");
        } else {
            asm volatile("cp.async.wait_group 0;" ::: "memory");
        }
        __syncthreads();

        const float* Kb = KV + (t & 1) * KT * DS;
        ull acc00 = 0, acc01 = 0, acc10 = 0, acc11 = 0;  // [qpair][key]

#pragma unroll
        for (int d = 0; d < DK; d += 4) {
            float4 k0 = *(const float4*)(Kb + (2 * kg + 0) * DS + d);
            float4 k1 = *(const float4*)(Kb + (2 * kg + 1) * DS + d);
#pragma unroll
            for (int dd = 0; dd < 4; dd++) {
                ull qp0, qp1;
                lds_v2u64(qp0, qp1, qt_base + (uint32_t)(((d + dd) * 16 + 4 * qg) * 4));
                float k0d = (dd == 0) ? k0.x : (dd == 1) ? k0.y : (dd == 2) ? k0.z : k0.w;
                float k1d = (dd == 0) ? k1.x : (dd == 1) ? k1.y : (dd == 2) ? k1.z : k1.w;
                ull k0p = dup2(k0d);
                ull k1p = dup2(k1d);
                fma2(acc00, qp0, k0p); fma2(acc01, qp0, k1p);
                fma2(acc10, qp1, k0p); fma2(acc11, qp1, k1p);
            }
        }
        // scatter scores into S: per query row, the two adjacent columns pack
        // into one STS.64 (halves of acc*0 / acc*1).
        {
            int col = t * KT + 2 * kg;
            float a00, a01, a10, a11, b00, b01, b10, b11;
            unpack2(acc00, a00, b00);  // (q 4qg+0, col), (q 4qg+1, col)
            unpack2(acc01, a01, b01);  // (q 4qg+0, col+1), (q 4qg+1, col+1)
            unpack2(acc10, a10, b10);  // (q 4qg+2, col), (q 4qg+3, col)
            unpack2(acc11, a11, b11);
            uint32_t base = s_base + (uint32_t)(col * 4);
            sts_u64(base + (uint32_t)((4*qg+0) * NTOK * 4), pack2(a00, a01));
            sts_u64(base + (uint32_t)((4*qg+1) * NTOK * 4), pack2(b00, b01));
            sts_u64(base + (uint32_t)((4*qg+2) * NTOK * 4), pack2(a10, a11));
            sts_u64(base + (uint32_t)((4*qg+3) * NTOK * 4), pack2(b10, b11));
        }
        __syncthreads();
    }

    // Prefetch V tile 0 (overlaps with softmax)
    load_tile_async(kv_base, 0, Vg);

    // ---- softmax over each of the 16 rows: warp w owns rows 2w, 2w+1 ----
    // float4-vectorized passes; S is left holding UNNORMALIZED exp values;
    // RL[r] = 1/rowsum.
    const int wid  = tid >> 5;
    const int lane = tid & 31;
#pragma unroll
    for (int rr = 0; rr < 2; rr++) {
        int r = wid * 2 + rr;
        float4* Sr = (float4*)(S + r * NTOK);

        float m = -1e30f;
#pragma unroll 4
        for (int j = lane; j < NTOK / 4; j += 32) {
            float4 s = Sr[j];
            m = fmaxf(m, fmaxf(fmaxf(s.x, s.y), fmaxf(s.z, s.w)));
        }
#pragma unroll
        for (int o = 16; o; o >>= 1) m = fmaxf(m, __shfl_xor_sync(~0u, m, o));

        float l = 0.f;
#pragma unroll 4
        for (int j = lane; j < NTOK / 4; j += 32) {
            float4 s = Sr[j];
            s.x = __expf(s.x - m);
            s.y = __expf(s.y - m);
            s.z = __expf(s.z - m);
            s.w = __expf(s.w - m);
            Sr[j] = s;
            l += (s.x + s.y) + (s.z + s.w);
        }
#pragma unroll
        for (int o = 16; o; o >>= 1) l += __shfl_xor_sync(~0u, l, o);
        if (lane == 0) RL[r] = 1.0f / l;
    }
    __syncthreads();

    // ---- P @ V on unnormalized P; final scale by RL[qi].
    //      Each thread: 1 query x 4 d-columns (2 x f32x2 accumulators).
    //      The normalized attn slab for tile t is streamed to gmem INSIDE the
    //      loop (2 STG.128/thread/iter) so store-issue hides under FFMA2. ----
    const int qi = tid >> 4;
    const int dg = (tid & 15) << 2;
    ull oacc0 = 0, oacc1 = 0;

    float* Ag = Attn + ((size_t)bh * NTOK + q0) * NTOK;

    for (int t = 0; t < NTILES; t++) {
        if (t + 1 < NTILES) {
            load_tile_async(kv_base, (t + 1) & 1, Vg + (size_t)(t + 1) * KT * DK);
            asm volatile("cp.async.wait_group 1;" ::: "memory");
        } else {
            asm volatile("cp.async.wait_group 0;" ::: "memory");
        }
        __syncthreads();

        // stream this tile's attn slab: rows 0..15, cols [t*KT, t*KT+128).
        // 512 float4s per tile, 2 per thread; each warp covers 128 consecutive
        // floats of one row (fully coalesced). Reads S (read-only here) + RL.
        if (write_attn) {
            int c0 = t * KT;
#pragma unroll
            for (int rep = 0; rep < 2; rep++) {
                int idx = tid + rep * THREADS;   // 0..511
                int r   = idx >> 5;              // row 0..15
                int c4  = (idx & 31) << 2;       // float offset within tile
                float inv = RL[r];
                float4 p = *(const float4*)(S + r * NTOK + c0 + c4);
                p.x *= inv; p.y *= inv; p.z *= inv; p.w *= inv;
                stg_cs128(Ag + r * NTOK + c0 + c4, p);
            }
        }

        const float* Vb = KV + (t & 1) * KT * DS;
        const float* Pr = S + qi * NTOK + t * KT;
        uint32_t vb_base = (uint32_t)__cvta_generic_to_shared(Vb);

#pragma unroll 4
        for (int j = 0; j < KT; j += 4) {
            float4 p = *(const float4*)(Pr + j);
#pragma unroll
            for (int jj = 0; jj < 4; jj++) {
                float pv = (jj == 0) ? p.x : (jj == 1) ? p.y : (jj == 2) ? p.z : p.w;
                ull pd = dup2(pv);
                ull v0, v1;
                lds_v2u64(v0, v1, vb_base + (uint32_t)(((j + jj) * DS + dg) * 4));
                fma2(oacc0, pd, v0);
                fma2(oacc1, pd, v1);
            }
        }
        __syncthreads();
    }

    {
        float inv = RL[qi];
        float4 o;
        unpack2(oacc0, o.x, o.y);
        unpack2(oacc1, o.z, o.w);
        o.x *= inv; o.y *= inv; o.z *= inv; o.w *= inv;
        stg_cs128(Out + ((size_t)bh * NTOK + q0 + qi) * DK + dg, o);
    }
}

extern "C" void kernel_launch(void* const* d_in, const int* in_sizes, int n_in,
                              void* d_out, int out_size) {
    const float* q = (const float*)d_in[0];
    const float* k = (const float*)d_in[1];
    const float* v = (const float*)d_in[2];
    float* out = (float*)d_out;

    const size_t out_elems = (size_t)BH * NTOK * DK;  // 4,194,304
    int write_attn = ((size_t)out_size > out_elems) ? 1 : 0;
    float* attn = write_attn ? (out + out_elems) : out;  // dummy ptr if attn not requested

    cudaFuncSetAttribute(sdpa_kernel, cudaFuncAttributeMaxDynamicSharedMemorySize,
                         SM_TOTAL * (int)sizeof(float));

    dim3 grid(NTOK / QT, BH);
    sdpa_kernel<<<grid, THREADS, SM_TOTAL * sizeof(float)>>>(q, k, v, out, attn, write_attn);
}

// round 16
// speedup vs baseline: 1.7039x; 1.7039x over previous
#include <cuda_runtime.h>
#include <cstdint>

#define BATCH   2
#define HEADS   16
#define NTOK    2048
#define DK      64
#define BH      (BATCH*HEADS)
#define QT      16              // queries per CTA
#define KT      128             // key/value tile rows
#define DS      68              // padded K/V smem row stride (floats)
#define SROW    2052            // padded S row stride (floats)
#define QTS     16              // Qt row stride
#define NTILES  (NTOK/KT)       // 16
#define THREADS 256
#define SCALE   0.125f          // 1/sqrt(64)

// smem layout (in floats)
#define SM_S    0                       // QT*SROW      = 32832
#define SM_QT   (QT*SROW)               // DK*QTS       = 1024
#define SM_KV   (SM_QT + DK*QTS)        // 2*KT*DS      = 17408 (double-buffered K/V; reused as reduce buf)
#define SM_RL   (SM_KV + 2*KT*DS)       // QT           = 16
#define SM_TOTAL (SM_RL + QT)           // 51280 floats = 205120 bytes

typedef unsigned long long ull;

__device__ __forceinline__ ull dup2(float x) {
    ull r; asm("mov.b64 %0, {%1,%1};" : "=l"(r) : "f"(x)); return r;
}
__device__ __forceinline__ void fma2(ull &d, ull a, ull b) {
    asm("fma.rn.f32x2 %0, %1, %2, %0;" : "+l"(d) : "l"(a), "l"(b));
}
__device__ __forceinline__ ull add2(ull a, ull b) {
    ull r; asm("add.rn.f32x2 %0, %1, %2;" : "=l"(r) : "l"(a), "l"(b)); return r;
}
__device__ __forceinline__ void unpack2(ull v, float &x, float &y) {
    asm("mov.b64 {%0,%1}, %2;" : "=f"(x), "=f"(y) : "l"(v));
}
__device__ __forceinline__ ull shfl_xor_u64(ull v, int m) {
    uint32_t lo, hi;
    asm("mov.b64 {%0,%1}, %2;" : "=r"(lo), "=r"(hi) : "l"(v));
    lo = __shfl_xor_sync(0xffffffffu, lo, m);
    hi = __shfl_xor_sync(0xffffffffu, hi, m);
    ull r; asm("mov.b64 %0, {%1,%2};" : "=l"(r) : "r"(lo), "r"(hi)); return r;
}
__device__ __forceinline__ void lds_v2u64(ull &a, ull &b, uint32_t addr) {
    asm volatile("ld.shared.v2.u64 {%0,%1}, [%2];" : "=l"(a), "=l"(b) : "r"(addr));
}
__device__ __forceinline__ void sts_u64(uint32_t addr, ull v) {
    asm volatile("st.shared.b64 [%0], %1;" :: "r"(addr), "l"(v) : "memory");
}
__device__ __forceinline__ void cpasync16(uint32_t dst, const float* src) {
    asm volatile("cp.async.cg.shared.global [%0], [%1], 16;" :: "r"(dst), "l"(src) : "memory");
}
__device__ __forceinline__ void stg_cs128(float* p, float4 v) {
    asm volatile("st.global.cs.v4.f32 [%0], {%1,%2,%3,%4};"
                 :: "l"(p), "f"(v.x), "f"(v.y), "f"(v.z), "f"(v.w) : "memory");
}
__device__ __forceinline__ float comp4(float4 v, int i) {
    return (i == 0) ? v.x : (i == 1) ? v.y : (i == 2) ? v.z : v.w;
}

// Load one KT x DK tile (row-major, stride DS floats) into smem buffer `buf` via cp.async.
__device__ __forceinline__ void load_tile_async(uint32_t kv_base, int buf, const float* __restrict__ src) {
    uint32_t dst0 = kv_base + (uint32_t)(buf * KT * DS * 4);
    int tid = threadIdx.x;
#pragma unroll
    for (int i = 0; i < (KT * DK / 4) / THREADS; i++) {
        int idx = tid + i * THREADS;
        int r = idx >> 4;
        int c = (idx & 15) << 2;
        cpasync16(dst0 + (uint32_t)((r * DS + c) * 4), src + r * DK + c);
    }
    asm volatile("cp.async.commit_group;" ::: "memory");
}

extern __shared__ float sm[];

__global__ void __launch_bounds__(THREADS, 1)
sdpa_kernel(const float* __restrict__ Q, const float* __restrict__ K,
            const float* __restrict__ V, float* __restrict__ Out,
            float* __restrict__ Attn, int write_attn)
{
    const int tid = threadIdx.x;
    const int w   = tid >> 5;
    const int ln  = tid & 31;
    const int bh  = blockIdx.y;
    const int q0  = blockIdx.x * QT;

    const float* Qg = Q + ((size_t)bh * NTOK + q0) * DK;
    const float* Kg = K + (size_t)bh * NTOK * DK;
    const float* Vg = V + (size_t)bh * NTOK * DK;

    float* S  = sm + SM_S;
    float* Qt = sm + SM_QT;
    float* KV = sm + SM_KV;
    float* RL = sm + SM_RL;
    uint32_t kv_base = (uint32_t)__cvta_generic_to_shared(KV);
    uint32_t qt_base = (uint32_t)__cvta_generic_to_shared(Qt);

    // Prefetch K tile 0
    load_tile_async(kv_base, 0, Kg);

    // Q transpose + pre-scale: Qt[d][q] = Q[q][d] * SCALE
    {
        int q  = tid & 15;
        int d0 = (tid >> 4) << 2;
        float4 v = *(const float4*)(Qg + q * DK + d0);
        Qt[(d0 + 0) * QTS + q] = v.x * SCALE;
        Qt[(d0 + 1) * QTS + q] = v.y * SCALE;
        Qt[(d0 + 2) * QTS + q] = v.z * SCALE;
        Qt[(d0 + 3) * QTS + q] = v.w * SCALE;
    }

    // ---- QK^T: lane tile = 4 queries x 4 keys, d split across warp halves ----
    // warp w: qg = w>>1 (queries 4qg..4qg+3)
    // keys: kx = (w&1)*64 + (ln&15); lane covers keys kx+16r, r=0..3 (STRIDED:
    // lane-to-lane row stride = 1 row = 68 floats -> bank +4/lane, conflict-free)
    // dh = ln>>4: d-range [dh*32, dh*32+32). Partner reduce via shfl.xor(16).
    const int qkQg = w >> 1;
    const int kx   = (w & 1) * 64 + (ln & 15);
    const int qkDh = ln >> 4;
    const int dBase = qkDh * 32;

    for (int t = 0; t < NTILES; t++) {
        if (t + 1 < NTILES) {
            load_tile_async(kv_base, (t + 1) & 1, Kg + (size_t)(t + 1) * KT * DK);
            asm volatile("cp.async.wait_group 1;" ::: "memory");
        } else {
            asm volatile("cp.async.wait_group 0;" ::: "memory");
        }
        __syncthreads();

        const float* Kb = KV + (t & 1) * KT * DS;
        ull acc[4][2];
#pragma unroll
        for (int i = 0; i < 4; i++) { acc[i][0] = 0; acc[i][1] = 0; }

#pragma unroll
        for (int dd4 = 0; dd4 < 8; dd4++) {
            int d0 = dBase + dd4 * 4;
            float4 kv0 = *(const float4*)(Kb + (kx +  0) * DS + d0);
            float4 kv1 = *(const float4*)(Kb + (kx + 16) * DS + d0);
            float4 kv2 = *(const float4*)(Kb + (kx + 32) * DS + d0);
            float4 kv3 = *(const float4*)(Kb + (kx + 48) * DS + d0);
            ull qp[4][2];
#pragma unroll
            for (int dd = 0; dd < 4; dd++)
                lds_v2u64(qp[dd][0], qp[dd][1],
                          qt_base + (uint32_t)((((d0 + dd) * QTS) + qkQg * 4) * 4));
#pragma unroll
            for (int dd = 0; dd < 4; dd++) {
                ull kp0 = dup2(comp4(kv0, dd));
                ull kp1 = dup2(comp4(kv1, dd));
                ull kp2 = dup2(comp4(kv2, dd));
                ull kp3 = dup2(comp4(kv3, dd));
                fma2(acc[0][0], qp[dd][0], kp0); fma2(acc[0][1], qp[dd][1], kp0);
                fma2(acc[1][0], qp[dd][0], kp1); fma2(acc[1][1], qp[dd][1], kp1);
                fma2(acc[2][0], qp[dd][0], kp2); fma2(acc[2][1], qp[dd][1], kp2);
                fma2(acc[3][0], qp[dd][0], kp3); fma2(acc[3][1], qp[dd][1], kp3);
            }
        }
        // reduce d-halves across lane pairs (ln, ln^16)
#pragma unroll
        for (int i = 0; i < 4; i++) {
            acc[i][0] = add2(acc[i][0], shfl_xor_u64(acc[i][0], 16));
            acc[i][1] = add2(acc[i][1], shfl_xor_u64(acc[i][1], 16));
        }
        if (qkDh == 0) {
            // scalar stores: for fixed (r, query) the 16 active lanes hit
            // consecutive columns -> conflict-free
            int colb = t * KT + kx;
#pragma unroll
            for (int r = 0; r < 4; r++) {
                float sA, sB, sC, sD;
                unpack2(acc[r][0], sA, sB);   // q 4qg+0, 4qg+1
                unpack2(acc[r][1], sC, sD);   // q 4qg+2, 4qg+3
                int col = colb + 16 * r;
                S[(qkQg * 4 + 0) * SROW + col] = sA;
                S[(qkQg * 4 + 1) * SROW + col] = sB;
                S[(qkQg * 4 + 2) * SROW + col] = sC;
                S[(qkQg * 4 + 3) * SROW + col] = sD;
            }
        }
        __syncthreads();
    }

    // Prefetch V tile 0 (overlaps with softmax)
    load_tile_async(kv_base, 0, Vg);

    // ---- softmax: warp w owns rows 2w, 2w+1; S left UNNORMALIZED; RL = 1/rowsum ----
#pragma unroll
    for (int rr = 0; rr < 2; rr++) {
        int r = w * 2 + rr;
        float4* Sr = (float4*)(S + r * SROW);

        float m = -1e30f;
#pragma unroll 4
        for (int j = ln; j < NTOK / 4; j += 32) {
            float4 s = Sr[j];
            m = fmaxf(m, fmaxf(fmaxf(s.x, s.y), fmaxf(s.z, s.w)));
        }
#pragma unroll
        for (int o = 16; o; o >>= 1) m = fmaxf(m, __shfl_xor_sync(~0u, m, o));

        float l = 0.f;
#pragma unroll 4
        for (int j = ln; j < NTOK / 4; j += 32) {
            float4 s = Sr[j];
            s.x = __expf(s.x - m);
            s.y = __expf(s.y - m);
            s.z = __expf(s.z - m);
            s.w = __expf(s.w - m);
            Sr[j] = s;
            l += (s.x + s.y) + (s.z + s.w);
        }
#pragma unroll
        for (int o = 16; o; o >>= 1) l += __shfl_xor_sync(~0u, l, o);
        if (ln == 0) RL[r] = 1.0f / l;
    }
    __syncthreads();

    // ---- P @ V: lane tile = 4 queries x 8 d-cols; warps split k 16-wide ----
    // Lane map chosen so every 8-lane LDS phase sees: V -> 4 distinct bank
    // groups (dg low bits), P -> 2 distinct bank groups (qg) -> conflict-free.
    const int pvQg = (ln & 1) | ((ln & 8) >> 2);          // 0..3
    const int pvDg = ((ln >> 1) & 3) | ((ln & 16) >> 2);  // 0..7
    const int kOff = w * 16;
    ull oacc[4][4];
#pragma unroll
    for (int i = 0; i < 4; i++)
#pragma unroll
        for (int j = 0; j < 4; j++) oacc[i][j] = 0;

    float* Ag = Attn + ((size_t)bh * NTOK + q0) * NTOK;

    for (int t = 0; t < NTILES; t++) {
        if (t + 1 < NTILES) {
            load_tile_async(kv_base, (t + 1) & 1, Vg + (size_t)(t + 1) * KT * DK);
            asm volatile("cp.async.wait_group 1;" ::: "memory");
        } else {
            asm volatile("cp.async.wait_group 0;" ::: "memory");
        }
        __syncthreads();

        // stream this tile's normalized attn slab (coalesced, evict-first)
        if (write_attn) {
            int c0 = t * KT;
#pragma unroll
            for (int rep = 0; rep < 2; rep++) {
                int idx = tid + rep * THREADS;   // 0..511
                int r   = idx >> 5;              // row 0..15
                int c4  = (idx & 31) << 2;       // 0..124
                float inv = RL[r];
                float4 p = *(const float4*)(S + r * SROW + c0 + c4);
                p.x *= inv; p.y *= inv; p.z *= inv; p.w *= inv;
                stg_cs128(Ag + r * NTOK + c0 + c4, p);
            }
        }

        const float* Vb = KV + (t & 1) * KT * DS;
        uint32_t vb_sh = (uint32_t)__cvta_generic_to_shared(Vb);

#pragma unroll
        for (int k4 = 0; k4 < 16; k4 += 4) {
            int k0 = kOff + k4;
            float4 pf[4];
#pragma unroll
            for (int qi = 0; qi < 4; qi++)
                pf[qi] = *(const float4*)(S + (pvQg * 4 + qi) * SROW + t * KT + k0);
#pragma unroll
            for (int kk = 0; kk < 4; kk++) {
                uint32_t va = vb_sh + (uint32_t)(((k0 + kk) * DS + pvDg * 8) * 4);
                ull v0, v1, v2, v3;
                lds_v2u64(v0, v1, va);
                lds_v2u64(v2, v3, va + 16);
#pragma unroll
                for (int qi = 0; qi < 4; qi++) {
                    ull pd = dup2(comp4(pf[qi], kk));
                    fma2(oacc[qi][0], pd, v0);
                    fma2(oacc[qi][1], pd, v1);
                    fma2(oacc[qi][2], pd, v2);
                    fma2(oacc[qi][3], pd, v3);
                }
            }
        }
        __syncthreads();
    }

    // ---- cross-warp k-reduction via smem (KV buffer is free now) ----
    {
        float* RED = KV;                 // 8 warps x 16q x 64d = 8192 floats
        uint32_t red_sh = (uint32_t)__cvta_generic_to_shared(RED);
        uint32_t base = red_sh + (uint32_t)((w * 1024) * 4);
#pragma unroll
        for (int qi = 0; qi < 4; qi++)
#pragma unroll
            for (int dp = 0; dp < 4; dp++)
                sts_u64(base + (uint32_t)((((pvQg * 4 + qi) * 64) + pvDg * 8 + dp * 2) * 4),
                        oacc[qi][dp]);
        __syncthreads();

        int q  = tid >> 4;
        int d4 = (tid & 15) << 2;
        float4 o = make_float4(0.f, 0.f, 0.f, 0.f);
#pragma unroll
        for (int w8 = 0; w8 < 8; w8++) {
            float4 r = *(const float4*)(RED + w8 * 1024 + q * 64 + d4);
            o.x += r.x; o.y += r.y; o.z += r.z; o.w += r.w;
        }
        float inv = RL[q];
        o.x *= inv; o.y *= inv; o.z *= inv; o.w *= inv;
        stg_cs128(Out + ((size_t)bh * NTOK + q0 + q) * DK + d4, o);
    }
}

extern "C" void kernel_launch(void* const* d_in, const int* in_sizes, int n_in,
                              void* d_out, int out_size) {
    const float* q = (const float*)d_in[0];
    const float* k = (const float*)d_in[1];
    const float* v = (const float*)d_in[2];
    float* out = (float*)d_out;

    const size_t out_elems = (size_t)BH * NTOK * DK;  // 4,194,304
    int write_attn = ((size_t)out_size > out_elems) ? 1 : 0;
    float* attn = write_attn ? (out + out_elems) : out;

    cudaFuncSetAttribute(sdpa_kernel, cudaFuncAttributeMaxDynamicSharedMemorySize,
                         SM_TOTAL * (int)sizeof(float));

    dim3 grid(NTOK / QT, BH);
    sdpa_kernel<<<grid, THREADS, SM_TOTAL * sizeof(float)>>>(q, k, v, out, attn, write_attn);
}